// round 1
// baseline (speedup 1.0000x reference)
#include <cuda_runtime.h>
#include <cuda_bf16.h>
#include <cstdint>

// Problem constants
#define B    2
#define N    4096
#define QD   1024
#define CD   1024
#define H    8
#define DH   64
#define INNER 512       // H*DH
#define NK   4097       // N+1

// ---------------- scratch (device globals; no allocs allowed) ----------------
__device__ float g_q [B * N  * INNER];   // [B,N,INNER]
__device__ float g_k [B * NK * INNER];   // [B,NK,INNER]
__device__ float g_v [B * NK * INNER];   // [B,NK,INNER]
__device__ float g_ao[B * N  * INNER];   // attention output [B,N,INNER]
__device__ float g_pooled[B * QD];       // mean over N of x
__device__ unsigned char g_mask[B * NK];

// ---------------- mean pool: pooled[b][d] = mean_n x[b][n][d] ----------------
__global__ void pooled_kernel(const float* __restrict__ x) {
    int id = blockIdx.x * blockDim.x + threadIdx.x;
    if (id >= B * QD) return;
    int b = id / QD, d = id % QD;
    const float* p = x + (size_t)b * N * QD + d;
    float s = 0.f;
    for (int n = 0; n < N; n++) s += p[(size_t)n * QD];
    g_pooled[id] = s * (1.0f / N);
}

// ---------------- mask conversion (uint8 or int32 layout, auto-detect) -------
__global__ void mask_conv_kernel(const unsigned char* __restrict__ m) {
    __shared__ int any_nonzero;
    if (threadIdx.x == 0) any_nonzero = 0;
    __syncthreads();
    // If mask is int32 little-endian 0/1, every byte at idx%4 != 0 is zero.
    // For a random uint8 0/1 mask this fails with overwhelming probability.
    int local = 0;
    for (int i = threadIdx.x; i < 8192; i += blockDim.x)
        if ((i & 3) && m[i]) local = 1;
    if (local) atomicOr(&any_nonzero, 1);
    __syncthreads();
    bool is_u8 = (any_nonzero != 0);
    const int* mi = (const int*)m;
    for (int j = threadIdx.x; j < B * NK; j += blockDim.x)
        g_mask[j] = is_u8 ? (m[j] != 0) : (mi[j] != 0);
}

// ---------------- background rows: k_bg = pooled @ Wk_bg, v_bg likewise ------
__global__ void bg_kernel(const float* __restrict__ Wkbg,
                          const float* __restrict__ Wvbg) {
    int id = blockIdx.x * blockDim.x + threadIdx.x;
    if (id >= B * INNER) return;
    int b = id / INNER, o = id % INNER;
    float sk = 0.f, sv = 0.f;
    for (int k = 0; k < QD; k++) {
        float pv = g_pooled[b * QD + k];
        sk += pv * Wkbg[(size_t)k * INNER + o];
        sv += pv * Wvbg[(size_t)k * INNER + o];
    }
    size_t base = ((size_t)(b * NK + N)) * INNER + o;
    g_k[base] = sk;
    g_v[base] = sv;
}

// ---------------- SGEMM: C[M,Nn] = A[M,K] @ Bm[K,Nn] (row-major) -------------
// Output rows can be remapped for the k/v concat: orow = (r/rpb)*(rpb+pad)+r%rpb
// Optional bias added per output column.
__global__ __launch_bounds__(256)
void sgemm128(const float* __restrict__ A, const float* __restrict__ Bm,
              float* __restrict__ C, int M, int Nn, int K,
              int rowsPerBatch, int rowPad, const float* __restrict__ bias)
{
    __shared__ __align__(16) float As[16][128];
    __shared__ __align__(16) float Bs[16][128];
    int tx = threadIdx.x & 15, ty = threadIdx.x >> 4;
    int m0 = blockIdx.y * 128, n0 = blockIdx.x * 128;

    float acc[8][8];
    #pragma unroll
    for (int i = 0; i < 8; i++)
        #pragma unroll
        for (int j = 0; j < 8; j++) acc[i][j] = 0.f;

    for (int k0 = 0; k0 < K; k0 += 16) {
        #pragma unroll
        for (int i = 0; i < 8; i++) {
            int idx = threadIdx.x + i * 256;          // 0..2047  (128 rows x 16 k)
            int r = idx >> 4, c = idx & 15;
            As[c][r] = A[(size_t)(m0 + r) * K + k0 + c];
        }
        #pragma unroll
        for (int i = 0; i < 8; i++) {
            int idx = threadIdx.x + i * 256;          // 16 k-rows x 128 cols
            int r = idx >> 7, c = idx & 127;
            Bs[r][c] = Bm[(size_t)(k0 + r) * Nn + n0 + c];
        }
        __syncthreads();
        #pragma unroll
        for (int kk = 0; kk < 16; kk++) {
            float4 a0 = *(const float4*)&As[kk][ty * 8];
            float4 a1 = *(const float4*)&As[kk][ty * 8 + 4];
            float4 b0 = *(const float4*)&Bs[kk][tx * 8];
            float4 b1 = *(const float4*)&Bs[kk][tx * 8 + 4];
            float a[8] = {a0.x,a0.y,a0.z,a0.w,a1.x,a1.y,a1.z,a1.w};
            float bb[8] = {b0.x,b0.y,b0.z,b0.w,b1.x,b1.y,b1.z,b1.w};
            #pragma unroll
            for (int i = 0; i < 8; i++)
                #pragma unroll
                for (int j = 0; j < 8; j++)
                    acc[i][j] += a[i] * bb[j];
        }
        __syncthreads();
    }

    #pragma unroll
    for (int i = 0; i < 8; i++) {
        int rr = m0 + ty * 8 + i;
        int orow = rr;
        if (rowPad) orow = (rr / rowsPerBatch) * (rowsPerBatch + rowPad) + rr % rowsPerBatch;
        float* crow = C + (size_t)orow * Nn + n0 + tx * 8;
        #pragma unroll
        for (int j = 0; j < 8; j++) {
            float v = acc[i][j];
            if (bias) v += bias[n0 + tx * 8 + j];
            crow[j] = v;
        }
    }
}

// ---------------- flash attention: 64-query x 64-key tiles -------------------
// grid: (N/64, B*H), 256 threads (16x16), each thread 4x4 microtiles.
#define PADQ 65
#define ATTN_SMEM ((4 * 64 * PADQ + 64 * 16) * 4)

__global__ __launch_bounds__(256)
void attn_kernel() {
    extern __shared__ float sm[];
    float* Qs  = sm;                    // 64 x PADQ
    float* Ks  = Qs + 64 * PADQ;
    float* Vs  = Ks + 64 * PADQ;
    float* Ps  = Vs + 64 * PADQ;
    float* red = Ps + 64 * PADQ;        // 64 x 16

    int tid = threadIdx.x;
    int tx = tid & 15, ty = tid >> 4;
    int b = blockIdx.y >> 3, h = blockIdx.y & 7;
    int qi0 = blockIdx.x * 64;
    const float scale = 0.125f;         // DH^-0.5

    // load Q tile
    #pragma unroll
    for (int i = 0; i < 16; i++) {
        int idx = tid + i * 256;        // 4096 = 64x64
        int r = idx >> 6, d = idx & 63;
        Qs[r * PADQ + d] = g_q[((size_t)(b * N + qi0 + r)) * INNER + h * 64 + d];
    }

    float m_[4], l_[4], O[4][4];
    #pragma unroll
    for (int i = 0; i < 4; i++) {
        m_[i] = -1e30f; l_[i] = 0.f;
        #pragma unroll
        for (int j = 0; j < 4; j++) O[i][j] = 0.f;
    }

    for (int kt = 0; kt < 65; kt++) {
        int j0 = kt * 64;
        __syncthreads();   // protect prior-iter reads of Ks/Vs/Ps
        #pragma unroll
        for (int i = 0; i < 16; i++) {
            int idx = tid + i * 256;
            int r = idx >> 6, d = idx & 63;
            int jg = j0 + r;
            float kv = 0.f, vv = 0.f;
            if (jg < NK) {
                size_t base = ((size_t)(b * NK + jg)) * INNER + h * 64 + d;
                kv = g_k[base]; vv = g_v[base];
            }
            Ks[r * PADQ + d] = kv;
            Vs[r * PADQ + d] = vv;
        }
        __syncthreads();

        // S = Q K^T (4x4 per thread)
        float s[4][4];
        #pragma unroll
        for (int i = 0; i < 4; i++)
            #pragma unroll
            for (int j = 0; j < 4; j++) s[i][j] = 0.f;
        #pragma unroll 8
        for (int d = 0; d < 64; d++) {
            float a[4], kk[4];
            #pragma unroll
            for (int i = 0; i < 4; i++) a[i]  = Qs[(ty * 4 + i) * PADQ + d];
            #pragma unroll
            for (int j = 0; j < 4; j++) kk[j] = Ks[(tx * 4 + j) * PADQ + d];
            #pragma unroll
            for (int i = 0; i < 4; i++)
                #pragma unroll
                for (int j = 0; j < 4; j++)
                    s[i][j] += a[i] * kk[j];
        }
        // scale + mask
        bool ok[4];
        #pragma unroll
        for (int j = 0; j < 4; j++) {
            int jg = j0 + tx * 4 + j;
            ok[j] = (jg < NK) && (g_mask[b * NK + jg] != 0);
        }
        #pragma unroll
        for (int i = 0; i < 4; i++)
            #pragma unroll
            for (int j = 0; j < 4; j++)
                s[i][j] = ok[j] ? s[i][j] * scale : -1e30f;

        // row max: partial per thread, reduce via smem
        #pragma unroll
        for (int i = 0; i < 4; i++) {
            float tm = s[i][0];
            #pragma unroll
            for (int j = 1; j < 4; j++) tm = fmaxf(tm, s[i][j]);
            red[(ty * 4 + i) * 16 + tx] = tm;
        }
        __syncthreads();
        float mn[4], alpha[4];
        #pragma unroll
        for (int i = 0; i < 4; i++) {
            int row = ty * 4 + i;
            float mm = -1e30f;
            #pragma unroll
            for (int t = 0; t < 16; t++) mm = fmaxf(mm, red[row * 16 + t]);
            mn[i] = fmaxf(m_[i], mm);
            alpha[i] = __expf(m_[i] - mn[i]);
            m_[i] = mn[i];
        }
        __syncthreads();   // before reusing red for sums

        // P = exp(S - m), partial row sums, stage P in smem
        #pragma unroll
        for (int i = 0; i < 4; i++) {
            int row = ty * 4 + i;
            float ts = 0.f;
            #pragma unroll
            for (int j = 0; j < 4; j++) {
                float p = __expf(s[i][j] - mn[i]);
                ts += p;
                Ps[row * PADQ + tx * 4 + j] = p;
            }
            red[row * 16 + tx] = ts;
        }
        __syncthreads();
        #pragma unroll
        for (int i = 0; i < 4; i++) {
            int row = ty * 4 + i;
            float rs = 0.f;
            #pragma unroll
            for (int t = 0; t < 16; t++) rs += red[row * 16 + t];
            l_[i] = l_[i] * alpha[i] + rs;
            #pragma unroll
            for (int j = 0; j < 4; j++) O[i][j] *= alpha[i];
        }
        // O += P @ V
        #pragma unroll 8
        for (int c = 0; c < 64; c++) {
            float p[4], vv[4];
            #pragma unroll
            for (int i = 0; i < 4; i++) p[i]  = Ps[(ty * 4 + i) * PADQ + c];
            #pragma unroll
            for (int j = 0; j < 4; j++) vv[j] = Vs[c * PADQ + tx * 4 + j];
            #pragma unroll
            for (int i = 0; i < 4; i++)
                #pragma unroll
                for (int j = 0; j < 4; j++)
                    O[i][j] += p[i] * vv[j];
        }
    }

    #pragma unroll
    for (int i = 0; i < 4; i++) {
        float inv = 1.0f / l_[i];
        int row = qi0 + ty * 4 + i;
        #pragma unroll
        for (int j = 0; j < 4; j++)
            g_ao[((size_t)(b * N + row)) * INNER + h * 64 + tx * 4 + j] = O[i][j] * inv;
    }
}

// ---------------- launch ----------------
extern "C" void kernel_launch(void* const* d_in, const int* in_sizes, int n_in,
                              void* d_out, int out_size) {
    const float* x    = (const float*)d_in[0];
    const float* ctx  = (const float*)d_in[1];
    const unsigned char* mask = (const unsigned char*)d_in[2];
    const float* Wq   = (const float*)d_in[3];
    const float* Wk   = (const float*)d_in[4];
    const float* Wv   = (const float*)d_in[5];
    const float* Wkbg = (const float*)d_in[6];
    const float* Wvbg = (const float*)d_in[7];
    const float* Wout = (const float*)d_in[8];
    const float* bout = (const float*)d_in[9];
    float* out = (float*)d_out;

    float *qptr, *kptr, *vptr, *aoptr;
    cudaGetSymbolAddress((void**)&qptr,  g_q);
    cudaGetSymbolAddress((void**)&kptr,  g_k);
    cudaGetSymbolAddress((void**)&vptr,  g_v);
    cudaGetSymbolAddress((void**)&aoptr, g_ao);

    cudaFuncSetAttribute(attn_kernel,
                         cudaFuncAttributeMaxDynamicSharedMemorySize, ATTN_SMEM);

    mask_conv_kernel<<<1, 256>>>(mask);
    pooled_kernel<<<(B * QD + 255) / 256, 256>>>(x);

    // q = x @ Wq
    sgemm128<<<dim3(INNER / 128, (B * N) / 128), 256>>>(
        x, Wq, qptr, B * N, INNER, QD, B * N, 0, nullptr);
    // k[:, :N] = context @ Wk   (rows remapped into NK-strided buffer)
    sgemm128<<<dim3(INNER / 128, (B * N) / 128), 256>>>(
        ctx, Wk, kptr, B * N, INNER, CD, N, 1, nullptr);
    // v[:, :N] = context @ Wv
    sgemm128<<<dim3(INNER / 128, (B * N) / 128), 256>>>(
        ctx, Wv, vptr, B * N, INNER, CD, N, 1, nullptr);
    // background row (row N of k/v)
    bg_kernel<<<(B * INNER + 255) / 256, 256>>>(Wkbg, Wvbg);

    // attention
    attn_kernel<<<dim3(N / 64, B * H), 256, ATTN_SMEM>>>();

    // out = ao @ Wout + b_out
    sgemm128<<<dim3(QD / 128, (B * N) / 128), 256>>>(
        aoptr, Wout, out, B * N, QD, INNER, B * N, 0, bout);
}